// round 4
// baseline (speedup 1.0000x reference)
#include <cuda_runtime.h>
#include <cuda_bf16.h>
#include <cstdint>

// ---------------- problem constants ----------------
#define BATCH 4
#define SQ    4096
#define SKV   4096
#define DIM   64
#define BM    128
#define BN    64
#define NT    (SKV / BN)
#define NTHREADS 256        // 8 warps: wm = w&3 (32 q-rows each), wn = w>>2 (32 kv-cols each)

// log2(e)/8 folded into Q at staging -> S is in log2 domain
#define SCALE2 0.18033688011112042f

#define SW128(o) ((uint32_t)(o) ^ ((((uint32_t)(o)) >> 3) & 0x70u))

__device__ __forceinline__ uint32_t smem_u32(const void* p) {
    return (uint32_t)__cvta_generic_to_shared(p);
}
__device__ __forceinline__ void ldsm_x4(uint32_t& r0, uint32_t& r1, uint32_t& r2, uint32_t& r3, uint32_t a) {
    asm volatile("ldmatrix.sync.aligned.m8n8.x4.shared.b16 {%0,%1,%2,%3}, [%4];"
                 : "=r"(r0), "=r"(r1), "=r"(r2), "=r"(r3) : "r"(a));
}
__device__ __forceinline__ void ldsm_x4_t(uint32_t& r0, uint32_t& r1, uint32_t& r2, uint32_t& r3, uint32_t a) {
    asm volatile("ldmatrix.sync.aligned.m8n8.x4.trans.shared.b16 {%0,%1,%2,%3}, [%4];"
                 : "=r"(r0), "=r"(r1), "=r"(r2), "=r"(r3) : "r"(a));
}
__device__ __forceinline__ void mma_bf16(float* c, const uint32_t* a, uint32_t b0, uint32_t b1) {
    asm volatile("mma.sync.aligned.m16n8k16.row.col.f32.bf16.bf16.f32 "
                 "{%0,%1,%2,%3}, {%4,%5,%6,%7}, {%8,%9}, {%0,%1,%2,%3};"
                 : "+f"(c[0]), "+f"(c[1]), "+f"(c[2]), "+f"(c[3])
                 : "r"(a[0]), "r"(a[1]), "r"(a[2]), "r"(a[3]), "r"(b0), "r"(b1));
}
__device__ __forceinline__ float ex2f(float x) {
    float y; asm("ex2.approx.ftz.f32 %0, %1;" : "=f"(y) : "f"(x)); return y;
}
__device__ __forceinline__ uint32_t packbf2(float lo, float hi) {
    __nv_bfloat162 t = __floats2bfloat162_rn(lo, hi);
    return *reinterpret_cast<uint32_t*>(&t);
}
__device__ __forceinline__ float sigmoidf_(float x) {
    float e = ex2f(-x * 1.4426950408889634f);
    return 1.0f / (1.0f + e);
}
#define STS128(addr, a_, b_, c_, d_) \
    asm volatile("st.shared.v4.b32 [%0], {%1,%2,%3,%4};" \
                 :: "r"(addr), "r"(a_), "r"(b_), "r"(c_), "r"(d_))

__global__ __launch_bounds__(NTHREADS, 1)
void attn_fused_kernel(const float* __restrict__ gq,
                       const float* __restrict__ gk,
                       const float* __restrict__ gv,
                       float* __restrict__ gout) {
    // lpsh: [2 halves][128 rows] softmax denominators
    __shared__ __align__(16) float lpsh[2][BM];
    // 4 x 8KB tiles (K0,K1,V0,V1), SW128 rows of 128B; also reused for:
    //   - Q staging (16KB) before the main loop
    //   - O-exchange (16KB) after the main loop
    __shared__ __align__(1024) __nv_bfloat16 sm_tiles[4 * 4096];

    const int tid = threadIdx.x;
    const int w   = tid >> 5;
    const int L   = tid & 31;
    const int wm  = w & 3;       // q group:  rows wm*32 .. wm*32+31
    const int wn  = w >> 2;      // kv half:  cols wn*32 .. wn*32+31
    const int b   = blockIdx.y;
    const int q0  = blockIdx.x * BM;

    const uint32_t tilesB = smem_u32(sm_tiles);
    const uint32_t kStage[2] = { tilesB,          tilesB + 8192  };
    const uint32_t vStage[2] = { tilesB + 16384,  tilesB + 24576 };

    // ---- Stage Q fp32 -> bf16 (pre-scaled), SW128 rows, in tiles region ----
    {
        const int row  = tid >> 1;
        const int half = (tid & 1) * 32;   // 32 cols = 64B
        const float4* g = (const float4*)(gq + ((size_t)b * SQ + q0 + row) * DIM + half);
        #pragma unroll
        for (int i = 0; i < 8; i++) {
            float4 f = g[i];
            uint32_t off = (uint32_t)(row * 128 + half * 2 + i * 8);
            uint2 pk;
            pk.x = packbf2(f.x * SCALE2, f.y * SCALE2);
            pk.y = packbf2(f.z * SCALE2, f.w * SCALE2);
            asm volatile("st.shared.v2.b32 [%0], {%1,%2};"
                         :: "r"(tilesB + SW128(off)), "r"(pk.x), "r"(pk.y));
        }
    }
    __syncthreads();

    // ---- Q fragments: 2 m16 tiles x 4 k-chunks ----
    uint32_t aq[2][4][4];
    {
        #pragma unroll
        for (int m = 0; m < 2; m++) {
            const int rr = wm * 32 + m * 16 + ((L >> 3) & 1) * 8 + (L & 7);
            #pragma unroll
            for (int kc = 0; kc < 4; kc++) {
                const int cc = 16 * kc + (L >> 4) * 8;
                ldsm_x4(aq[m][kc][0], aq[m][kc][1], aq[m][kc][2], aq[m][kc][3],
                        tilesB + SW128((uint32_t)(rr * 128 + cc * 2)));
            }
        }
    }
    __syncthreads();   // Q staging consumed; region becomes K/V stages

    // ---- accumulators ----
    float oa[2][8][4];
    #pragma unroll
    for (int m = 0; m < 2; m++)
        #pragma unroll
        for (int j = 0; j < 8; j++)
            #pragma unroll
            for (int i = 0; i < 4; i++) oa[m][j][i] = 0.0f;
    float lp[2][2] = {{0.0f, 0.0f}, {0.0f, 0.0f}};

    // ---- gmem tile load mapping ----
    const int ldrow = tid >> 2;
    const float4* gk4 = (const float4*)(gk + ((size_t)b * SKV + ldrow) * DIM + (tid & 3) * 16);
    const float4* gv4 = (const float4*)(gv + ((size_t)b * SKV + ldrow) * DIM + (tid & 3) * 16);
    const size_t tileF4 = (size_t)BN * DIM / 4;
    const uint32_t so  = (uint32_t)(ldrow * 128 + (tid & 3) * 32);
    const uint32_t sw0 = SW128(so), sw1 = SW128(so + 16);

    float4 k0, k1, k2, k3, v0, v1, v2, v3;
    #define LOAD_TILE(t) do { const size_t _o = (size_t)(t) * tileF4;            \
        k0 = gk4[_o+0]; k1 = gk4[_o+1]; k2 = gk4[_o+2]; k3 = gk4[_o+3];          \
        v0 = gv4[_o+0]; v1 = gv4[_o+1]; v2 = gv4[_o+2]; v3 = gv4[_o+3]; } while(0)
    #define STORE_TILE(s) do {                                                   \
        STS128(kStage[s] + sw0, packbf2(k0.x,k0.y), packbf2(k0.z,k0.w),          \
                                packbf2(k1.x,k1.y), packbf2(k1.z,k1.w));         \
        STS128(kStage[s] + sw1, packbf2(k2.x,k2.y), packbf2(k2.z,k2.w),          \
                                packbf2(k3.x,k3.y), packbf2(k3.z,k3.w));         \
        STS128(vStage[s] + sw0, packbf2(v0.x,v0.y), packbf2(v0.z,v0.w),          \
                                packbf2(v1.x,v1.y), packbf2(v1.z,v1.w));         \
        STS128(vStage[s] + sw1, packbf2(v2.x,v2.y), packbf2(v2.z,v2.w),          \
                                packbf2(v3.x,v3.y), packbf2(v3.z,v3.w)); } while(0)

    // ldmatrix lane-address pieces
    const int kq_r  = (L & 7);
    const int kq_c8 = (L >> 3) * 8;
    const int v_r   = ((L >> 3) & 1) * 8 + (L & 7);
    const int v_c8  = (L >> 4) * 8;

    LOAD_TILE(0);
    STORE_TILE(0);
    LOAD_TILE(1);

    for (int n = 0; n < NT; n++) {
        __syncthreads();   // stage (n&1) fully stored; stage ((n+1)&1) fully consumed
        const uint32_t skB = kStage[n & 1];
        const uint32_t svB = vStage[n & 1];

        // ---- S = Q @ K^T : per warp 32q x 32kv; each ldsm feeds both m tiles ----
        float sc[2][4][4];
        #pragma unroll
        for (int m = 0; m < 2; m++)
            #pragma unroll
            for (int j = 0; j < 4; j++)
                #pragma unroll
                for (int i = 0; i < 4; i++) sc[m][j][i] = 0.0f;

        #pragma unroll
        for (int j = 0; j < 4; j++) {
            const int rr = wn * 32 + 8 * j + kq_r;
            #pragma unroll
            for (int kc2 = 0; kc2 < 2; kc2++) {
                uint32_t b0, b1, b2, b3;
                const int cc = 32 * kc2 + kq_c8;
                ldsm_x4(b0, b1, b2, b3, skB + SW128((uint32_t)(rr * 128 + cc * 2)));
                #pragma unroll
                for (int m = 0; m < 2; m++) {
                    mma_bf16(sc[m][j], aq[m][2 * kc2],     b0, b1);
                    mma_bf16(sc[m][j], aq[m][2 * kc2 + 1], b2, b3);
                }
            }
        }

        // ---- softmax: p = 2^s; accumulate denominators; pack P as A-fragments ----
        uint32_t ap[2][2][4];
        #pragma unroll
        for (int m = 0; m < 2; m++) {
            #pragma unroll
            for (int j = 0; j < 4; j++) {
                float p0 = ex2f(sc[m][j][0]);
                float p1 = ex2f(sc[m][j][1]);
                float p2 = ex2f(sc[m][j][2]);
                float p3 = ex2f(sc[m][j][3]);
                lp[m][0] += p0 + p1;
                lp[m][1] += p2 + p3;
                const int kcp = j >> 1;
                if ((j & 1) == 0) {
                    ap[m][kcp][0] = packbf2(p0, p1);
                    ap[m][kcp][1] = packbf2(p2, p3);
                } else {
                    ap[m][kcp][2] = packbf2(p0, p1);
                    ap[m][kcp][3] = packbf2(p2, p3);
                }
            }
        }

        // ---- O += P @ V : per warp (32q x 64d) over its 32 kv rows ----
        #pragma unroll
        for (int kcp = 0; kcp < 2; kcp++) {
            const int rr = wn * 32 + 16 * kcp + v_r;
            #pragma unroll
            for (int j2 = 0; j2 < 8; j2 += 2) {
                uint32_t b0, b1, b2, b3;
                const int cc = 8 * j2 + v_c8;
                ldsm_x4_t(b0, b1, b2, b3, svB + SW128((uint32_t)(rr * 128 + cc * 2)));
                #pragma unroll
                for (int m = 0; m < 2; m++) {
                    mma_bf16(oa[m][j2],     ap[m][kcp], b0, b1);
                    mma_bf16(oa[m][j2 + 1], ap[m][kcp], b2, b3);
                }
            }
        }

        // ---- prefetch pipeline ----
        if (n + 1 < NT) {
            STORE_TILE((n + 1) & 1);
            if (n + 2 < NT) LOAD_TILE(n + 2);
        }
    }

    // ---- softmax denominators: quad-reduce, publish per (half, row) ----
    #pragma unroll
    for (int m = 0; m < 2; m++)
        #pragma unroll
        for (int h = 0; h < 2; h++) {
            float x = lp[m][h];
            x += __shfl_xor_sync(0xFFFFFFFFu, x, 1);
            x += __shfl_xor_sync(0xFFFFFFFFu, x, 2);
            lp[m][h] = x;
        }
    __syncthreads();   // tiles region done; reuse for O exchange
    if ((L & 3) == 0) {
        const int rbase = wm * 32 + (L >> 2);
        lpsh[wn][rbase +  0] = lp[0][0];
        lpsh[wn][rbase +  8] = lp[0][1];
        lpsh[wn][rbase + 16] = lp[1][0];
        lpsh[wn][rbase + 24] = lp[1][1];
    }

    // ---- O exchange: warp (wm,wn) keeps m=wn tile, ships the other to its peer ----
    // slot(wm, s): 4KB each, lane-interleaved float4 (conflict-free)
    {
        const int ship = 1 - wn;   // m tile this warp does NOT epilogue
        const uint32_t slot = tilesB + (uint32_t)(wm * 2 + ship) * 4096;
        #pragma unroll
        for (int j = 0; j < 8; j++) {
            STS128(slot + (uint32_t)(j * 32 + L) * 16,
                   __float_as_uint(oa[ship][j][0]), __float_as_uint(oa[ship][j][1]),
                   __float_as_uint(oa[ship][j][2]), __float_as_uint(oa[ship][j][3]));
        }
    }
    __syncthreads();
    {
        const uint32_t slot = tilesB + (uint32_t)(wm * 2 + wn) * 4096;
        #pragma unroll
        for (int j = 0; j < 8; j++) {
            uint4 u = *reinterpret_cast<const uint4*>(
                &sm_tiles[((size_t)(wm * 2 + wn) * 4096 + (j * 32 + L) * 16) / 2]);
            (void)slot;
            oa[wn][j][0] += __uint_as_float(u.x);
            oa[wn][j][1] += __uint_as_float(u.y);
            oa[wn][j][2] += __uint_as_float(u.z);
            oa[wn][j][3] += __uint_as_float(u.w);
        }
    }

    // ---- epilogue: warp (wm,wn) owns rows wm*32 + wn*16 + {0..15} ----
    const int r0 = q0 + wm * 32 + wn * 16 + (L >> 2);
    const int r1 = r0 + 8;
    const int lr0 = wm * 32 + wn * 16 + (L >> 2);
    const float inv0 = 1.0f / (lpsh[0][lr0] + lpsh[1][lr0]);
    const float inv1 = 1.0f / (lpsh[0][lr0 + 8] + lpsh[1][lr0 + 8]);

    const float* q0p = gq + ((size_t)b * SQ + r0) * DIM;
    const float* q1p = gq + ((size_t)b * SQ + r1) * DIM;
    float* o0p = gout + ((size_t)b * SQ + r0) * DIM;
    float* o1p = gout + ((size_t)b * SQ + r1) * DIM;

    #pragma unroll
    for (int j = 0; j < 8; j++) {
        const int d0 = 8 * j + 2 * (L & 3);
        float2 qa = *(const float2*)(q0p + d0);
        float2 qb = *(const float2*)(q1p + d0);
        float o0 = oa[wn][j][0] * inv0 + qa.x;
        float o1 = oa[wn][j][1] * inv0 + qa.y;
        float o2 = oa[wn][j][2] * inv1 + qb.x;
        float o3 = oa[wn][j][3] * inv1 + qb.y;
        #pragma unroll
        for (int it = 0; it < 3; it++) {
            o0 = sigmoidf_(o0 + 2.0f * qa.x);
            o1 = sigmoidf_(o1 + 2.0f * qa.y);
            o2 = sigmoidf_(o2 + 2.0f * qb.x);
            o3 = sigmoidf_(o3 + 2.0f * qb.y);
            o0 = fminf(fmaxf(o0, 0.0f), 1.0f);
            o1 = fminf(fmaxf(o1, 0.0f), 1.0f);
            o2 = fminf(fmaxf(o2, 0.0f), 1.0f);
            o3 = fminf(fmaxf(o3, 0.0f), 1.0f);
        }
        *(float2*)(o0p + d0) = make_float2(o0, o1);
        *(float2*)(o1p + d0) = make_float2(o2, o3);
    }
}

extern "C" void kernel_launch(void* const* d_in, const int* in_sizes, int n_in,
                              void* d_out, int out_size) {
    const float* q = (const float*)d_in[0];
    const float* k = (const float*)d_in[1];
    const float* v = (const float*)d_in[2];
    float* out = (float*)d_out;

    dim3 grid(SQ / BM, BATCH);
    attn_fused_kernel<<<grid, NTHREADS>>>(q, k, v, out);
}

// round 5
// speedup vs baseline: 1.7621x; 1.7621x over previous
#include <cuda_runtime.h>
#include <cuda_bf16.h>
#include <cstdint>

// ---------------- problem constants ----------------
#define BATCH 4
#define SQ    4096
#define SKV   4096
#define DIM   64
#define BM    128
#define BN    64
#define NT    (SKV / BN)
#define NTHREADS 512        // 16 warps: wq = w>>1 (16 q-rows), wn = w&1 (32 kv-cols)

// log2(e)/8 folded into Q at staging -> S is in log2 domain
#define SCALE2 0.18033688011112042f

#define SW128(o) ((uint32_t)(o) ^ ((((uint32_t)(o)) >> 3) & 0x70u))

__device__ __forceinline__ uint32_t smem_u32(const void* p) {
    return (uint32_t)__cvta_generic_to_shared(p);
}
__device__ __forceinline__ void ldsm_x4(uint32_t& r0, uint32_t& r1, uint32_t& r2, uint32_t& r3, uint32_t a) {
    asm volatile("ldmatrix.sync.aligned.m8n8.x4.shared.b16 {%0,%1,%2,%3}, [%4];"
                 : "=r"(r0), "=r"(r1), "=r"(r2), "=r"(r3) : "r"(a));
}
__device__ __forceinline__ void ldsm_x4_t(uint32_t& r0, uint32_t& r1, uint32_t& r2, uint32_t& r3, uint32_t a) {
    asm volatile("ldmatrix.sync.aligned.m8n8.x4.trans.shared.b16 {%0,%1,%2,%3}, [%4];"
                 : "=r"(r0), "=r"(r1), "=r"(r2), "=r"(r3) : "r"(a));
}
__device__ __forceinline__ void mma_bf16(float* c, const uint32_t* a, uint32_t b0, uint32_t b1) {
    asm volatile("mma.sync.aligned.m16n8k16.row.col.f32.bf16.bf16.f32 "
                 "{%0,%1,%2,%3}, {%4,%5,%6,%7}, {%8,%9}, {%0,%1,%2,%3};"
                 : "+f"(c[0]), "+f"(c[1]), "+f"(c[2]), "+f"(c[3])
                 : "r"(a[0]), "r"(a[1]), "r"(a[2]), "r"(a[3]), "r"(b0), "r"(b1));
}
__device__ __forceinline__ float ex2f(float x) {
    float y; asm("ex2.approx.ftz.f32 %0, %1;" : "=f"(y) : "f"(x)); return y;
}
__device__ __forceinline__ uint32_t packbf2(float lo, float hi) {
    __nv_bfloat162 t = __floats2bfloat162_rn(lo, hi);
    return *reinterpret_cast<uint32_t*>(&t);
}
__device__ __forceinline__ float sigmoidf_(float x) {
    float e = ex2f(-x * 1.4426950408889634f);
    return 1.0f / (1.0f + e);
}
#define STS128(addr, a_, b_, c_, d_) \
    asm volatile("st.shared.v4.b32 [%0], {%1,%2,%3,%4};" \
                 :: "r"(addr), "r"(a_), "r"(b_), "r"(c_), "r"(d_))
#define LDS128(a_, b_, c_, d_, addr) \
    asm volatile("ld.shared.v4.b32 {%0,%1,%2,%3}, [%4];" \
                 : "=r"(a_), "=r"(b_), "=r"(c_), "=r"(d_) : "r"(addr))

__global__ __launch_bounds__(NTHREADS, 1)
void attn_fused_kernel(const float* __restrict__ gq,
                       const float* __restrict__ gk,
                       const float* __restrict__ gv,
                       float* __restrict__ gout) {
    // softmax denominators: [kv-half][row]
    __shared__ __align__(16) float lpsh[2][BM];
    // 4 x 8KB tiles (K0,K1,V0,V1), SW128 128B rows; reused for Q staging (16KB)
    // before the loop and the O exchange (32KB) after it.
    __shared__ __align__(1024) __nv_bfloat16 sm_tiles[4 * 4096];

    const int tid = threadIdx.x;
    const int w   = tid >> 5;
    const int L   = tid & 31;
    const int wq  = w >> 1;      // q group: rows wq*16 .. wq*16+15
    const int wn  = w & 1;       // kv half: cols wn*32 .. wn*32+31
    const int b   = blockIdx.y;
    const int q0  = blockIdx.x * BM;

    const uint32_t tilesB = smem_u32(sm_tiles);
    const uint32_t kStage[2] = { tilesB,          tilesB + 8192  };
    const uint32_t vStage[2] = { tilesB + 16384,  tilesB + 24576 };

    // ---- Stage Q fp32 -> bf16 (pre-scaled), SW128 rows, in tiles region ----
    {
        const int row  = tid >> 2;               // 0..127
        const int cblk = (tid & 3) * 16;         // 16 cols = 4 float4
        const float4* g = (const float4*)(gq + ((size_t)b * SQ + q0 + row) * DIM + cblk);
        float4 f0 = g[0], f1 = g[1], f2 = g[2], f3 = g[3];
        const uint32_t o0 = (uint32_t)(row * 128 + cblk * 2);
        STS128(tilesB + SW128(o0),
               packbf2(f0.x * SCALE2, f0.y * SCALE2), packbf2(f0.z * SCALE2, f0.w * SCALE2),
               packbf2(f1.x * SCALE2, f1.y * SCALE2), packbf2(f1.z * SCALE2, f1.w * SCALE2));
        STS128(tilesB + SW128(o0 + 16),
               packbf2(f2.x * SCALE2, f2.y * SCALE2), packbf2(f2.z * SCALE2, f2.w * SCALE2),
               packbf2(f3.x * SCALE2, f3.y * SCALE2), packbf2(f3.z * SCALE2, f3.w * SCALE2));
    }
    __syncthreads();

    // ---- Q fragments: 4 k-chunks of m16n8k16 A (16 regs) ----
    uint32_t aq[4][4];
    {
        const int rr = wq * 16 + ((L >> 3) & 1) * 8 + (L & 7);
        #pragma unroll
        for (int kc = 0; kc < 4; kc++) {
            const int cc = 16 * kc + (L >> 4) * 8;
            ldsm_x4(aq[kc][0], aq[kc][1], aq[kc][2], aq[kc][3],
                    tilesB + SW128((uint32_t)(rr * 128 + cc * 2)));
        }
    }
    __syncthreads();   // Q staging consumed; region becomes K/V stages

    // ---- accumulators ----
    float oa[8][4];
    #pragma unroll
    for (int j = 0; j < 8; j++)
        #pragma unroll
        for (int i = 0; i < 4; i++) oa[j][i] = 0.0f;
    float lp0 = 0.0f, lp1 = 0.0f;

    // ---- gmem tile load mapping: 512 threads, each 8 floats of K and of V ----
    const int ldrow = tid >> 3;                  // 0..63
    const int ldcb  = (tid & 7) * 8;             // 8-col block
    const float4* gk4 = (const float4*)(gk + ((size_t)b * SKV + ldrow) * DIM + ldcb);
    const float4* gv4 = (const float4*)(gv + ((size_t)b * SKV + ldrow) * DIM + ldcb);
    const size_t tileF4 = (size_t)BN * DIM / 4;
    const uint32_t swT = SW128((uint32_t)(ldrow * 128 + ldcb * 2));

    float4 k0, k1, v0, v1;
    #define LOAD_TILE(t) do { const size_t _o = (size_t)(t) * tileF4;            \
        k0 = gk4[_o+0]; k1 = gk4[_o+1];                                          \
        v0 = gv4[_o+0]; v1 = gv4[_o+1]; } while(0)
    #define STORE_TILE(s) do {                                                   \
        STS128(kStage[s] + swT, packbf2(k0.x,k0.y), packbf2(k0.z,k0.w),          \
                                packbf2(k1.x,k1.y), packbf2(k1.z,k1.w));         \
        STS128(vStage[s] + swT, packbf2(v0.x,v0.y), packbf2(v0.z,v0.w),          \
                                packbf2(v1.x,v1.y), packbf2(v1.z,v1.w)); } while(0)

    // ldmatrix lane-address pieces
    const int kq_r  = (L & 7);
    const int kq_c8 = (L >> 3) * 8;
    const int v_r   = ((L >> 3) & 1) * 8 + (L & 7);
    const int v_c8  = (L >> 4) * 8;

    LOAD_TILE(0);
    STORE_TILE(0);
    LOAD_TILE(1);

    for (int n = 0; n < NT; n++) {
        __syncthreads();   // stage (n&1) stored; stage ((n+1)&1) consumed
        const uint32_t skB = kStage[n & 1];
        const uint32_t svB = vStage[n & 1];

        // ---- S = Q @ K^T : 16q x 32kv per warp ----
        float sc[4][4];
        #pragma unroll
        for (int j = 0; j < 4; j++)
            #pragma unroll
            for (int i = 0; i < 4; i++) sc[j][i] = 0.0f;

        #pragma unroll
        for (int j = 0; j < 4; j++) {
            const int rr = wn * 32 + 8 * j + kq_r;
            #pragma unroll
            for (int kc2 = 0; kc2 < 2; kc2++) {
                uint32_t b0, b1, b2, b3;
                const int cc = 32 * kc2 + kq_c8;
                ldsm_x4(b0, b1, b2, b3, skB + SW128((uint32_t)(rr * 128 + cc * 2)));
                mma_bf16(sc[j], aq[2 * kc2],     b0, b1);
                mma_bf16(sc[j], aq[2 * kc2 + 1], b2, b3);
            }
        }

        // ---- softmax: p = 2^s; accumulate denominators; pack P as A-fragments ----
        uint32_t ap[2][4];
        #pragma unroll
        for (int j = 0; j < 4; j++) {
            float p0 = ex2f(sc[j][0]);
            float p1 = ex2f(sc[j][1]);
            float p2 = ex2f(sc[j][2]);
            float p3 = ex2f(sc[j][3]);
            lp0 += p0 + p1;
            lp1 += p2 + p3;
            const int kcp = j >> 1;
            if ((j & 1) == 0) {
                ap[kcp][0] = packbf2(p0, p1);
                ap[kcp][1] = packbf2(p2, p3);
            } else {
                ap[kcp][2] = packbf2(p0, p1);
                ap[kcp][3] = packbf2(p2, p3);
            }
        }

        // ---- O += P @ V : 16q x 64d per warp over its 32 kv rows ----
        #pragma unroll
        for (int kcp = 0; kcp < 2; kcp++) {
            const int rr = wn * 32 + 16 * kcp + v_r;
            #pragma unroll
            for (int j2 = 0; j2 < 8; j2 += 2) {
                uint32_t b0, b1, b2, b3;
                const int cc = 8 * j2 + v_c8;
                ldsm_x4_t(b0, b1, b2, b3, svB + SW128((uint32_t)(rr * 128 + cc * 2)));
                mma_bf16(oa[j2],     ap[kcp], b0, b1);
                mma_bf16(oa[j2 + 1], ap[kcp], b2, b3);
            }
        }

        // ---- prefetch pipeline ----
        if (n + 1 < NT) {
            STORE_TILE((n + 1) & 1);
            if (n + 2 < NT) LOAD_TILE(n + 2);
        }
    }

    // ---- softmax denominators: quad-reduce; publish per (half,row) ----
    lp0 += __shfl_xor_sync(0xFFFFFFFFu, lp0, 1);
    lp0 += __shfl_xor_sync(0xFFFFFFFFu, lp0, 2);
    lp1 += __shfl_xor_sync(0xFFFFFFFFu, lp1, 1);
    lp1 += __shfl_xor_sync(0xFFFFFFFFu, lp1, 2);
    __syncthreads();   // all warps done with tile stages
    if ((L & 3) == 0) {
        const int rbase = wq * 16 + (L >> 2);
        lpsh[wn][rbase]     = lp0;
        lpsh[wn][rbase + 8] = lp1;
    }

    // ---- O exchange: warp (wq,wn) keeps d-half wn, ships d-half 1-wn ----
    // slot(wq,h): 2KB, holds shipped contribution for d-half h of q-group wq.
    {
        const int ship = 1 - wn;
        const uint32_t slot = tilesB + (uint32_t)(wq * 2 + ship) * 2048;
        #pragma unroll
        for (int jp = 0; jp < 4; jp++) {
            const int j = ship * 4 + jp;
            STS128(slot + (uint32_t)(jp * 32 + L) * 16,
                   __float_as_uint(oa[j][0]), __float_as_uint(oa[j][1]),
                   __float_as_uint(oa[j][2]), __float_as_uint(oa[j][3]));
        }
    }
    __syncthreads();
    {
        const uint32_t slot = tilesB + (uint32_t)(wq * 2 + wn) * 2048;
        #pragma unroll
        for (int jp = 0; jp < 4; jp++) {
            const int j = wn * 4 + jp;
            uint32_t x, y, z, u;
            LDS128(x, y, z, u, slot + (uint32_t)(jp * 32 + L) * 16);
            oa[j][0] += __uint_as_float(x);
            oa[j][1] += __uint_as_float(y);
            oa[j][2] += __uint_as_float(z);
            oa[j][3] += __uint_as_float(u);
        }
    }

    // ---- epilogue: warp (wq,wn) owns rows wq*16+{0..15}, d-cols wn*32..+31 ----
    const int lr0 = wq * 16 + (L >> 2);
    const float inv0 = 1.0f / (lpsh[0][lr0] + lpsh[1][lr0]);
    const float inv1 = 1.0f / (lpsh[0][lr0 + 8] + lpsh[1][lr0 + 8]);

    const int r0 = q0 + lr0;
    const int r1 = r0 + 8;
    const float* q0p = gq + ((size_t)b * SQ + r0) * DIM;
    const float* q1p = gq + ((size_t)b * SQ + r1) * DIM;
    float* o0p = gout + ((size_t)b * SQ + r0) * DIM;
    float* o1p = gout + ((size_t)b * SQ + r1) * DIM;

    #pragma unroll
    for (int jp = 0; jp < 4; jp++) {
        const int j  = wn * 4 + jp;
        const int d0 = 8 * j + 2 * (L & 3);
        float2 qa = *(const float2*)(q0p + d0);
        float2 qb = *(const float2*)(q1p + d0);
        float o0 = oa[j][0] * inv0 + qa.x;
        float o1 = oa[j][1] * inv0 + qa.y;
        float o2 = oa[j][2] * inv1 + qb.x;
        float o3 = oa[j][3] * inv1 + qb.y;
        #pragma unroll
        for (int it = 0; it < 3; it++) {
            o0 = sigmoidf_(o0 + 2.0f * qa.x);
            o1 = sigmoidf_(o1 + 2.0f * qa.y);
            o2 = sigmoidf_(o2 + 2.0f * qb.x);
            o3 = sigmoidf_(o3 + 2.0f * qb.y);
            o0 = fminf(fmaxf(o0, 0.0f), 1.0f);
            o1 = fminf(fmaxf(o1, 0.0f), 1.0f);
            o2 = fminf(fmaxf(o2, 0.0f), 1.0f);
            o3 = fminf(fmaxf(o3, 0.0f), 1.0f);
        }
        *(float2*)(o0p + d0) = make_float2(o0, o1);
        *(float2*)(o1p + d0) = make_float2(o2, o3);
    }
}

extern "C" void kernel_launch(void* const* d_in, const int* in_sizes, int n_in,
                              void* d_out, int out_size) {
    const float* q = (const float*)d_in[0];
    const float* k = (const float*)d_in[1];
    const float* v = (const float*)d_in[2];
    float* out = (float*)d_out;

    dim3 grid(SQ / BM, BATCH);
    attn_fused_kernel<<<grid, NTHREADS>>>(q, k, v, out);
}